// round 3
// baseline (speedup 1.0000x reference)
#include <cuda_runtime.h>
#include <math.h>

#define HH 512
#define WW 512
#define CC 64
#define HW (HH*WW)
#define TILE 32              // 32x32 spatial tile, 4 px/thread
#define HALO 2
#define SXD (TILE + 2*HALO)  // 36
#define SXP 38               // padded, EVEN row stride (8B-aligned pair loads)
#define CI_CHUNK 8
#define CO_BLK 16
#define SX_FLOATS (CI_CHUNK * SXD * SXP)            // 10944
#define SX_BYTES  (SX_FLOATS * 4)                   // 43776 (16B multiple)
#define SW2_ELEMS (CI_CHUNK * 9 * CO_BLK)           // 1152 ull
#define SMEM_BYTES (SX_BYTES + SW2_ELEMS * 8)       // 52992

typedef unsigned long long ull;

__device__ float g_xori[CC * HW];
__device__ unsigned char g_md[HW];

__device__ __forceinline__ int reflect512(int i) {
    i = abs(i);
    return min(i, 1022 - i);
}

__device__ __forceinline__ float gelu_exact(float v) {
    return 0.5f * v * (1.0f + erff(v * 0.70710678118654752f));
}

__device__ __forceinline__ ull splat2(float x) {
    ull r;
    asm("mov.b64 %0, {%1, %1};" : "=l"(r) : "f"(x));
    return r;
}
__device__ __forceinline__ void ffma2(ull& a, ull x, ull w) {
    asm("fma.rn.f32x2 %0, %1, %2, %0;" : "+l"(a) : "l"(x), "l"(w));
}
__device__ __forceinline__ float2 unpack2(ull a) {
    float2 f;
    asm("mov.b64 {%0, %1}, %2;" : "=f"(f.x), "=f"(f.y) : "l"(a));
    return f;
}

// ---------------------------------------------------------------------------
__global__ void md_kernel(const float* __restrict__ mask) {
    int x = blockIdx.x * 32 + threadIdx.x;
    int y = blockIdx.y * 8 + threadIdx.y;
    float m = 0.0f;
    #pragma unroll
    for (int dy = -2; dy <= 2; dy++) {
        int yy = y + dy;
        if (yy < 0 || yy >= HH) continue;
        #pragma unroll
        for (int dx = -2; dx <= 2; dx++) {
            int xx = x + dx;
            if (xx < 0 || xx >= WW) continue;
            m = fmaxf(m, mask[yy * WW + xx]);
        }
    }
    g_md[y * WW + x] = (m > 0.5f) ? 1 : 0;
}

// ---------------------------------------------------------------------------
// MODE 1: in = x       -> g_xori = md ? gelu(conv+b1) : x
// MODE 2: in = g_xori  -> d_out[sd] = gelu(conv+b2) + x
// Packing: f32x2 over adjacent pixel COLUMNS (natural LDS.64), weights
// pre-splatted {w,w} in smem (broadcast LDS.128). Zero pack/splat MOVs in
// the hot loop. 4 px/thread (rows ly, ly+16; cols 2lx, 2lx+1).
// ---------------------------------------------------------------------------
template <int MODE>
__global__ void __launch_bounds__(256, 2) conv_kernel(
    const float* __restrict__ xres,
    const float* __restrict__ wgt,    // (64,64,3,3) OIHW
    const float* __restrict__ bias,
    const float* __restrict__ mask,
    float* __restrict__ out)
{
    extern __shared__ __align__(16) char dsm[];
    float (*sx)[SXD][SXP] = reinterpret_cast<float(*)[SXD][SXP]>(dsm);
    ull* sw2 = reinterpret_cast<ull*>(dsm + SX_BYTES);

    const float* in = (MODE == 1) ? xres : (const float*)g_xori;

    const int tid = threadIdx.x;
    const int lx = tid & 15;
    const int ly = tid >> 4;
    const int bx = blockIdx.x * TILE;
    const int by = blockIdx.y * TILE;
    const int co0 = blockIdx.z * CO_BLK;

    const int warp = tid >> 5;
    const int lane = tid & 31;
    const int gxa = reflect512(bx - 2 + lane);
    const int gxb = reflect512(bx - 2 + lane + 32);

    ull accA[CO_BLK], accB[CO_BLK];
    #pragma unroll
    for (int i = 0; i < CO_BLK; i++) { accA[i] = 0ull; accB[i] = 0ull; }

    for (int cc = 0; cc < CC; cc += CI_CHUNK) {
        // --- stage input plane: one warp per ci, no div/mod ---
        {
            const float* src = in + (cc + warp) * HW;
            #pragma unroll 4
            for (int r = 0; r < SXD; r++) {
                const float* rowp = src + reflect512(by - 2 + r) * WW;
                sx[warp][r][lane] = rowp[gxa];
                if (lane < SXD - 32) sx[warp][r][lane + 32] = rowp[gxb];
            }
        }
        // --- stage weights, pre-splatted {w,w} ---
        for (int idx = tid; idx < SW2_ELEMS; idx += 256) {
            int co   = idx & 15;
            int rest = idx >> 4;      // ci*9 + k
            int ci   = rest / 9;
            int k    = rest - ci * 9;
            sw2[idx] = splat2(wgt[(co0 + co) * (CC * 9) + (cc + ci) * 9 + k]);
        }
        __syncthreads();

        #pragma unroll 2
        for (int ci = 0; ci < CI_CHUNK; ci++) {
            #pragma unroll
            for (int k = 0; k < 9; k++) {
                const int dy = (k / 3) * 2;
                const int dx = (k % 3) * 2;
                ull xa = *reinterpret_cast<const ull*>(&sx[ci][ly + dy][2 * lx + dx]);
                ull xb = *reinterpret_cast<const ull*>(&sx[ci][ly + 16 + dy][2 * lx + dx]);
                const ulonglong2* wp =
                    reinterpret_cast<const ulonglong2*>(&sw2[(ci * 9 + k) * CO_BLK]);
                #pragma unroll
                for (int j = 0; j < 8; j++) {
                    ulonglong2 w = wp[j];
                    ffma2(accA[2 * j],     xa, w.x);
                    ffma2(accA[2 * j + 1], xa, w.y);
                    ffma2(accB[2 * j],     xb, w.x);
                    ffma2(accB[2 * j + 1], xb, w.y);
                }
            }
        }
        __syncthreads();
    }

    // --- epilogue: 2 row groups x (2 adjacent cols packed) x 16 co ---
    const int cx = bx + 2 * lx;
    #pragma unroll
    for (int pr = 0; pr < 2; pr++) {
        const int gy = by + ly + 16 * pr;
        const int p = gy * WW + cx;
        const ull* a = pr ? accB : accA;

        if (MODE == 1) {
            const bool m0 = (g_md[p] != 0);
            const bool m1 = (g_md[p + 1] != 0);
            #pragma unroll
            for (int j = 0; j < CO_BLK; j++) {
                float2 v = unpack2(a[j]);
                const int c = co0 + j;
                const float b = bias[c];
                const int o = c * HW + p;
                float2 xr = *reinterpret_cast<const float2*>(&xres[o]);
                float2 w;
                w.x = m0 ? gelu_exact(v.x + b) : xr.x;
                w.y = m1 ? gelu_exact(v.y + b) : xr.y;
                *reinterpret_cast<float2*>(&g_xori[o]) = w;
            }
        } else {
            const bool s0 = mask[p] > 0.5f;
            const bool s1 = mask[p + 1] > 0.5f;
            if (s0 || s1) {
                #pragma unroll
                for (int j = 0; j < CO_BLK; j++) {
                    float2 v = unpack2(a[j]);
                    const int c = co0 + j;
                    const float b = bias[c];
                    const int o = c * HW + p;
                    if (s0 && s1) {
                        float2 xr = *reinterpret_cast<const float2*>(&xres[o]);
                        float2 w;
                        w.x = gelu_exact(v.x + b) + xr.x;
                        w.y = gelu_exact(v.y + b) + xr.y;
                        *reinterpret_cast<float2*>(&out[o]) = w;
                    } else if (s0) {
                        out[o] = gelu_exact(v.x + b) + xres[o];
                    } else {
                        out[o + 1] = gelu_exact(v.y + b) + xres[o + 1];
                    }
                }
            }
        }
    }
}

// ---------------------------------------------------------------------------
__global__ void dw_kernel(
    const float* __restrict__ x,
    const float* __restrict__ w3,
    const float* __restrict__ b3,
    const float* __restrict__ mask,
    float* __restrict__ out)
{
    int gx = blockIdx.x * 256 + threadIdx.x;
    int gy = blockIdx.y;
    int c  = blockIdx.z;
    int p  = gy * WW + gx;
    if (mask[p] > 0.5f) return;

    const float* wc = w3 + c * 9;
    const float* xc = x + c * HW;
    float a = 0.0f;
    #pragma unroll
    for (int k = 0; k < 9; k++) {
        int yy = reflect512(gy + (k / 3) * 2 - 2);
        int xx = reflect512(gx + (k % 3) * 2 - 2);
        a = fmaf(xc[yy * WW + xx], wc[k], a);
    }
    out[c * HW + p] = gelu_exact(a + b3[c]) + xc[p];
}

// ---------------------------------------------------------------------------
extern "C" void kernel_launch(void* const* d_in, const int* in_sizes, int n_in,
                              void* d_out, int out_size) {
    const float* x    = (const float*)d_in[0];
    const float* mask = (const float*)d_in[1];
    const float* w1   = (const float*)d_in[2];
    const float* b1   = (const float*)d_in[3];
    const float* w2   = (const float*)d_in[4];
    const float* b2   = (const float*)d_in[5];
    const float* w3   = (const float*)d_in[6];
    const float* b3   = (const float*)d_in[7];
    float* out = (float*)d_out;

    static bool attr_set = false;
    if (!attr_set) {
        cudaFuncSetAttribute(conv_kernel<1>,
            cudaFuncAttributeMaxDynamicSharedMemorySize, SMEM_BYTES);
        cudaFuncSetAttribute(conv_kernel<2>,
            cudaFuncAttributeMaxDynamicSharedMemorySize, SMEM_BYTES);
        attr_set = true;
    }

    md_kernel<<<dim3(WW / 32, HH / 8), dim3(32, 8)>>>(mask);

    dim3 cgrid(WW / TILE, HH / TILE, CC / CO_BLK);   // 16 x 16 x 4
    conv_kernel<1><<<cgrid, 256, SMEM_BYTES>>>(x, w1, b1, mask, out);

    dw_kernel<<<dim3(WW / 256, HH, CC), 256>>>(x, w3, b3, mask, out);

    conv_kernel<2><<<cgrid, 256, SMEM_BYTES>>>(x, w2, b2, mask, out);
}

// round 4
// speedup vs baseline: 1.1053x; 1.1053x over previous
#include <cuda_runtime.h>
#include <math.h>

#define HH 512
#define WW 512
#define CC 64
#define HW (HH*WW)
#define TILE 32              // 32x32 spatial tile, 4 px/thread
#define HALO 2
#define SXD (TILE + 2*HALO)  // 36
#define SXP 38               // padded, EVEN row stride
#define CI_CHUNK 8
#define CO_BLK 16
#define SX_FLOATS (CI_CHUNK * SXD * SXP)            // 10944
#define SX_BYTES  (SX_FLOATS * 4)                   // 43776
#define SW2_ELEMS (CI_CHUNK * 9 * CO_BLK)           // 1152 ull
#define SMEM_BYTES (SX_BYTES + SW2_ELEMS * 8)       // 52992

typedef unsigned long long ull;

__device__ float g_xori[CC * HW];
__device__ unsigned char g_md[HW];

__device__ __forceinline__ int reflect512(int i) {
    i = abs(i);
    return min(i, 1022 - i);
}

__device__ __forceinline__ float gelu_exact(float v) {
    return 0.5f * v * (1.0f + erff(v * 0.70710678118654752f));
}

__device__ __forceinline__ ull splat2(float x) {
    ull r;
    asm("mov.b64 %0, {%1, %1};" : "=l"(r) : "f"(x));
    return r;
}
__device__ __forceinline__ void ffma2(ull& a, ull x, ull w) {
    asm("fma.rn.f32x2 %0, %1, %2, %0;" : "+l"(a) : "l"(x), "l"(w));
}
__device__ __forceinline__ float2 unpack2(ull a) {
    float2 f;
    asm("mov.b64 {%0, %1}, %2;" : "=f"(f.x), "=f"(f.y) : "l"(a));
    return f;
}

// ---------------------------------------------------------------------------
__global__ void md_kernel(const float* __restrict__ mask) {
    int x = blockIdx.x * 32 + threadIdx.x;
    int y = blockIdx.y * 8 + threadIdx.y;
    float m = 0.0f;
    #pragma unroll
    for (int dy = -2; dy <= 2; dy++) {
        int yy = y + dy;
        if (yy < 0 || yy >= HH) continue;
        #pragma unroll
        for (int dx = -2; dx <= 2; dx++) {
            int xx = x + dx;
            if (xx < 0 || xx >= WW) continue;
            m = fmaxf(m, mask[yy * WW + xx]);
        }
    }
    g_md[y * WW + x] = (m > 0.5f) ? 1 : 0;
}

// ---------------------------------------------------------------------------
// MODE 1: in = x       -> g_xori = md ? gelu(conv+b1) : x
// MODE 2: in = g_xori  -> d_out[sd] = gelu(conv+b2) + x
// f32x2 packed over adjacent pixel columns (natural LDS.64); weights
// pre-splatted {w,w} in smem (broadcast LDS.128). Deep unroll (ci x4, k x9)
// for latency hiding — only 4 warps/SMSP resident.
// ---------------------------------------------------------------------------
template <int MODE>
__global__ void __launch_bounds__(256, 2) conv_kernel(
    const float* __restrict__ xres,
    const float* __restrict__ wgt,    // (64,64,3,3) OIHW
    const float* __restrict__ bias,
    const float* __restrict__ mask,
    float* __restrict__ out)
{
    extern __shared__ __align__(16) char dsm[];
    float (*sx)[SXD][SXP] = reinterpret_cast<float(*)[SXD][SXP]>(dsm);
    ull* sw2 = reinterpret_cast<ull*>(dsm + SX_BYTES);

    const float* in = (MODE == 1) ? xres : (const float*)g_xori;

    const int tid = threadIdx.x;
    const int lx = tid & 15;
    const int ly = tid >> 4;
    const int bx = blockIdx.x * TILE;
    const int by = blockIdx.y * TILE;
    const int co0 = blockIdx.z * CO_BLK;

    const int warp = tid >> 5;
    const int lane = tid & 31;
    const bool col_interior = (bx != 0) && (bx != WW - TILE);
    const int gxa = reflect512(bx - 2 + lane);
    const int gxb = reflect512(bx - 2 + lane + 32);

    ull accA[CO_BLK], accB[CO_BLK];
    #pragma unroll
    for (int i = 0; i < CO_BLK; i++) { accA[i] = 0ull; accB[i] = 0ull; }

    for (int cc = 0; cc < CC; cc += CI_CHUNK) {
        // --- stage input plane: one warp per ci ---
        {
            const float* src = in + (cc + warp) * HW;
            if (col_interior) {
                // contiguous, 8B-aligned: lanes 0..17 each move one float2/row
                if (lane < 18) {
                    #pragma unroll 4
                    for (int r = 0; r < SXD; r++) {
                        const float* rowp = src + reflect512(by - 2 + r) * WW + (bx - 2);
                        float2 v = *reinterpret_cast<const float2*>(rowp + 2 * lane);
                        *reinterpret_cast<float2*>(&sx[warp][r][2 * lane]) = v;
                    }
                }
            } else {
                #pragma unroll 4
                for (int r = 0; r < SXD; r++) {
                    const float* rowp = src + reflect512(by - 2 + r) * WW;
                    sx[warp][r][lane] = rowp[gxa];
                    if (lane < SXD - 32) sx[warp][r][lane + 32] = rowp[gxb];
                }
            }
        }
        // --- stage weights, pre-splatted {w,w} ---
        for (int idx = tid; idx < SW2_ELEMS; idx += 256) {
            int co   = idx & 15;
            int rest = idx >> 4;      // ci*9 + k
            int ci   = rest / 9;
            int k    = rest - ci * 9;
            sw2[idx] = splat2(wgt[(co0 + co) * (CC * 9) + (cc + ci) * 9 + k]);
        }
        __syncthreads();

        #pragma unroll 4
        for (int ci = 0; ci < CI_CHUNK; ci++) {
            #pragma unroll
            for (int k = 0; k < 9; k++) {
                const int dy = (k / 3) * 2;
                const int dx = (k % 3) * 2;
                ull xa = *reinterpret_cast<const ull*>(&sx[ci][ly + dy][2 * lx + dx]);
                ull xb = *reinterpret_cast<const ull*>(&sx[ci][ly + 16 + dy][2 * lx + dx]);
                const ulonglong2* wp =
                    reinterpret_cast<const ulonglong2*>(&sw2[(ci * 9 + k) * CO_BLK]);
                #pragma unroll
                for (int j = 0; j < 8; j++) {
                    ulonglong2 w = wp[j];
                    ffma2(accA[2 * j],     xa, w.x);
                    ffma2(accA[2 * j + 1], xa, w.y);
                    ffma2(accB[2 * j],     xb, w.x);
                    ffma2(accB[2 * j + 1], xb, w.y);
                }
            }
        }
        __syncthreads();
    }

    // --- epilogue: 2 row groups x (2 adjacent cols packed) x 16 co ---
    const int cx = bx + 2 * lx;
    #pragma unroll
    for (int pr = 0; pr < 2; pr++) {
        const int gy = by + ly + 16 * pr;
        const int p = gy * WW + cx;
        const ull* a = pr ? accB : accA;

        if (MODE == 1) {
            const bool m0 = (g_md[p] != 0);
            const bool m1 = (g_md[p + 1] != 0);
            #pragma unroll
            for (int j = 0; j < CO_BLK; j++) {
                float2 v = unpack2(a[j]);
                const int c = co0 + j;
                const float b = bias[c];
                const int o = c * HW + p;
                float2 xr = *reinterpret_cast<const float2*>(&xres[o]);
                float2 w;
                w.x = m0 ? gelu_exact(v.x + b) : xr.x;
                w.y = m1 ? gelu_exact(v.y + b) : xr.y;
                *reinterpret_cast<float2*>(&g_xori[o]) = w;
            }
        } else {
            const bool s0 = mask[p] > 0.5f;
            const bool s1 = mask[p + 1] > 0.5f;
            if (s0 || s1) {
                #pragma unroll
                for (int j = 0; j < CO_BLK; j++) {
                    float2 v = unpack2(a[j]);
                    const int c = co0 + j;
                    const float b = bias[c];
                    const int o = c * HW + p;
                    if (s0 && s1) {
                        float2 xr = *reinterpret_cast<const float2*>(&xres[o]);
                        float2 w;
                        w.x = gelu_exact(v.x + b) + xr.x;
                        w.y = gelu_exact(v.y + b) + xr.y;
                        *reinterpret_cast<float2*>(&out[o]) = w;
                    } else if (s0) {
                        out[o] = gelu_exact(v.x + b) + xres[o];
                    } else {
                        out[o + 1] = gelu_exact(v.y + b) + xres[o + 1];
                    }
                }
            }
        }
    }
}

// ---------------------------------------------------------------------------
__global__ void dw_kernel(
    const float* __restrict__ x,
    const float* __restrict__ w3,
    const float* __restrict__ b3,
    const float* __restrict__ mask,
    float* __restrict__ out)
{
    int gx = blockIdx.x * 256 + threadIdx.x;
    int gy = blockIdx.y;
    int c  = blockIdx.z;
    int p  = gy * WW + gx;
    if (mask[p] > 0.5f) return;

    const float* wc = w3 + c * 9;
    const float* xc = x + c * HW;
    float a = 0.0f;
    #pragma unroll
    for (int k = 0; k < 9; k++) {
        int yy = reflect512(gy + (k / 3) * 2 - 2);
        int xx = reflect512(gx + (k % 3) * 2 - 2);
        a = fmaf(xc[yy * WW + xx], wc[k], a);
    }
    out[c * HW + p] = gelu_exact(a + b3[c]) + xc[p];
}

// ---------------------------------------------------------------------------
extern "C" void kernel_launch(void* const* d_in, const int* in_sizes, int n_in,
                              void* d_out, int out_size) {
    const float* x    = (const float*)d_in[0];
    const float* mask = (const float*)d_in[1];
    const float* w1   = (const float*)d_in[2];
    const float* b1   = (const float*)d_in[3];
    const float* w2   = (const float*)d_in[4];
    const float* b2   = (const float*)d_in[5];
    const float* w3   = (const float*)d_in[6];
    const float* b3   = (const float*)d_in[7];
    float* out = (float*)d_out;

    static bool attr_set = false;
    if (!attr_set) {
        cudaFuncSetAttribute(conv_kernel<1>,
            cudaFuncAttributeMaxDynamicSharedMemorySize, SMEM_BYTES);
        cudaFuncSetAttribute(conv_kernel<2>,
            cudaFuncAttributeMaxDynamicSharedMemorySize, SMEM_BYTES);
        attr_set = true;
    }

    md_kernel<<<dim3(WW / 32, HH / 8), dim3(32, 8)>>>(mask);

    dim3 cgrid(WW / TILE, HH / TILE, CC / CO_BLK);   // 16 x 16 x 4
    conv_kernel<1><<<cgrid, 256, SMEM_BYTES>>>(x, w1, b1, mask, out);

    dw_kernel<<<dim3(WW / 256, HH, CC), 256>>>(x, w3, b3, mask, out);

    conv_kernel<2><<<cgrid, 256, SMEM_BYTES>>>(x, w2, b2, mask, out);
}